// round 1
// baseline (speedup 1.0000x reference)
#include <cuda_runtime.h>

#define BB 4
#define SS_ 2048
#define EE 1024
#define HH 128

#define NEG_INF (-1e30f)

// Scratch for projected q/k/v (device globals: no allocation allowed).
__device__ float g_q[BB * SS_ * HH];
__device__ float g_k[BB * SS_ * HH];
__device__ float g_v[BB * SS_ * HH];

// ---------------------------------------------------------------------------
// Projection GEMM: O[M,H] = X[M,E] @ W[E,H], M = B*S = 8192.
// blockIdx.y selects which of Wq/Wk/Wv.  BM=64, BN=128(=H), BK=16.
// 256 threads, 4x8 micro-tile per thread.
// ---------------------------------------------------------------------------
__global__ __launch_bounds__(256, 1) void proj_kernel(
    const float* __restrict__ x,
    const float* __restrict__ Wq,
    const float* __restrict__ Wk,
    const float* __restrict__ Wv)
{
    constexpr int BM = 64;
    constexpr int BK = 16;
    __shared__ float sXT[BK][68];   // [k][row], stride 68 (16B aligned, low-conflict)
    __shared__ float sW[BK][HH];    // [k][col]

    const int which = blockIdx.y;
    const float* __restrict__ W = (which == 0) ? Wq : (which == 1) ? Wk : Wv;
    float* __restrict__ O = (which == 0) ? g_q : (which == 1) ? g_k : g_v;

    const int m0  = blockIdx.x * BM;
    const int tid = threadIdx.x;
    const int ty  = tid >> 4;   // 0..15 -> 4-row group
    const int tx  = tid & 15;   // 0..15 -> 8-col group

    float acc[4][8];
#pragma unroll
    for (int i = 0; i < 4; i++)
#pragma unroll
        for (int j = 0; j < 8; j++) acc[i][j] = 0.f;

    const int lrow = tid >> 2;  // 0..63
    const int lkq  = tid & 3;   // 0..3  (float4 index along k)

    for (int k0 = 0; k0 < EE; k0 += BK) {
        // Load X tile (64 x 16), store transposed.
        float4 xv = *(const float4*)(x + (size_t)(m0 + lrow) * EE + k0 + lkq * 4);
        sXT[lkq * 4 + 0][lrow] = xv.x;
        sXT[lkq * 4 + 1][lrow] = xv.y;
        sXT[lkq * 4 + 2][lrow] = xv.z;
        sXT[lkq * 4 + 3][lrow] = xv.w;
        // Load W tile (16 x 128).
#pragma unroll
        for (int p = 0; p < 2; p++) {
            int idx = p * 256 + tid;
            int row = idx >> 5;
            int hq  = idx & 31;
            *(float4*)&sW[row][hq * 4] =
                *(const float4*)(W + (size_t)(k0 + row) * HH + hq * 4);
        }
        __syncthreads();

#pragma unroll
        for (int kk = 0; kk < BK; kk++) {
            float4 xr = *(float4*)&sXT[kk][ty * 4];
            float4 w0 = *(float4*)&sW[kk][tx * 8];
            float4 w1 = *(float4*)&sW[kk][tx * 8 + 4];
            float xs[4] = {xr.x, xr.y, xr.z, xr.w};
            float ws[8] = {w0.x, w0.y, w0.z, w0.w, w1.x, w1.y, w1.z, w1.w};
#pragma unroll
            for (int i = 0; i < 4; i++)
#pragma unroll
                for (int j = 0; j < 8; j++)
                    acc[i][j] += xs[i] * ws[j];
        }
        __syncthreads();
    }

#pragma unroll
    for (int i = 0; i < 4; i++) {
        int row = m0 + ty * 4 + i;
        float4 o0 = make_float4(acc[i][0], acc[i][1], acc[i][2], acc[i][3]);
        float4 o1 = make_float4(acc[i][4], acc[i][5], acc[i][6], acc[i][7]);
        *(float4*)(O + (size_t)row * HH + tx * 8)     = o0;
        *(float4*)(O + (size_t)row * HH + tx * 8 + 4) = o1;
    }
}

// ---------------------------------------------------------------------------
// Flash attention, fp32, causal.
// Block = (batch b, pair p). Handles q-tiles t=p and t=63-p (load balance).
// TQ=32, TK=64, 256 threads = 8 warps.
// Warp w owns query rows w*4..w*4+3; lane owns key cols {lane, lane+32}
// and output cols lane*4..lane*4+3.  Softmax stats are warp-register-local.
// ---------------------------------------------------------------------------
__global__ __launch_bounds__(256, 1) void attn_kernel(float* __restrict__ out)
{
    constexpr int TQ = 32;
    constexpr int TK = 64;
    constexpr int KSTR = 65;  // sKT row stride (odd: 4-way store conflict, cf-free reads)

    extern __shared__ float sm[];
    float* sQ  = sm;                       // 32*128  = 4096
    float* sKT = sQ + TQ * HH;             // 128*65  = 8320  [h][key]
    float* sV  = sKT + HH * KSTR;          // 64*128  = 8192  [key][h]
    float* sS  = sV + TK * HH;             // 32*64   = 2048  [qrow][key]

    const int b    = blockIdx.y;
    const int pr   = blockIdx.x;
    const int tid  = threadIdx.x;
    const int wid  = tid >> 5;
    const int lane = tid & 31;

    const float scale = 0.08838834764831845f;  // 1/sqrt(128)

    const float* __restrict__ qbase = g_q + (size_t)b * SS_ * HH;
    const float* __restrict__ kbase = g_k + (size_t)b * SS_ * HH;
    const float* __restrict__ vbase = g_v + (size_t)b * SS_ * HH;

    for (int half = 0; half < 2; half++) {
        const int t  = (half == 0) ? pr : (63 - pr);
        const int q0 = t * TQ;

        __syncthreads();  // previous half fully done before sQ overwrite

        // Load Q tile (32 x 128)
#pragma unroll
        for (int p = 0; p < 4; p++) {
            int idx = p * 256 + tid;
            int row = idx >> 5;
            int hq  = idx & 31;
            *(float4*)&sQ[row * HH + hq * 4] =
                *(const float4*)(qbase + (size_t)(q0 + row) * HH + hq * 4);
        }

        float m_i[4], l_i[4], acc[4][4];
#pragma unroll
        for (int i = 0; i < 4; i++) {
            m_i[i] = NEG_INF;
            l_i[i] = 0.f;
#pragma unroll
            for (int j = 0; j < 4; j++) acc[i][j] = 0.f;
        }

        const int nkt = (q0 + TQ - 1) / TK + 1;
        for (int kt = 0; kt < nkt; kt++) {
            const int k0 = kt * TK;
            __syncthreads();  // prev tile's PV readers done; Q visible on kt==0

            // Load K (transposed) + V tiles (64 x 128 each)
#pragma unroll
            for (int p = 0; p < 8; p++) {
                int idx = p * 256 + tid;
                int row = idx >> 5;   // key row 0..63 (fixed per warp -> coalesced)
                int hq  = idx & 31;
                float4 kv = *(const float4*)(kbase + (size_t)(k0 + row) * HH + hq * 4);
                sKT[(hq * 4 + 0) * KSTR + row] = kv.x;
                sKT[(hq * 4 + 1) * KSTR + row] = kv.y;
                sKT[(hq * 4 + 2) * KSTR + row] = kv.z;
                sKT[(hq * 4 + 3) * KSTR + row] = kv.w;
                *(float4*)&sV[row * HH + hq * 4] =
                    *(const float4*)(vbase + (size_t)(k0 + row) * HH + hq * 4);
            }
            __syncthreads();

            // ---- S = Q K^T  (each thread: 4 rows x 2 cols) ----
            float s0[4] = {0.f, 0.f, 0.f, 0.f};
            float s1[4] = {0.f, 0.f, 0.f, 0.f};
#pragma unroll 4
            for (int h4 = 0; h4 < HH; h4 += 4) {
                float qrow[4][4];
#pragma unroll
                for (int i = 0; i < 4; i++) {
                    float4 qv = *(float4*)&sQ[(wid * 4 + i) * HH + h4];
                    qrow[i][0] = qv.x; qrow[i][1] = qv.y;
                    qrow[i][2] = qv.z; qrow[i][3] = qv.w;
                }
#pragma unroll
                for (int hh = 0; hh < 4; hh++) {
                    float kA = sKT[(h4 + hh) * KSTR + lane];
                    float kB = sKT[(h4 + hh) * KSTR + lane + 32];
#pragma unroll
                    for (int i = 0; i < 4; i++) {
                        s0[i] += qrow[i][hh] * kA;
                        s1[i] += qrow[i][hh] * kB;
                    }
                }
            }

            // ---- scale + causal mask + online softmax (warp-local) ----
            const int kc0 = k0 + lane;
            const int kc1 = k0 + lane + 32;
#pragma unroll
            for (int i = 0; i < 4; i++) {
                const int qi = q0 + wid * 4 + i;
                float v0 = (kc0 <= qi) ? s0[i] * scale : NEG_INF;
                float v1 = (kc1 <= qi) ? s1[i] * scale : NEG_INF;
                float mx = fmaxf(v0, v1);
#pragma unroll
                for (int off = 16; off >= 1; off >>= 1)
                    mx = fmaxf(mx, __shfl_xor_sync(0xffffffffu, mx, off));
                float m_new = fmaxf(m_i[i], mx);
                float alpha = __expf(m_i[i] - m_new);
                float p0 = __expf(v0 - m_new);
                float p1 = __expf(v1 - m_new);
                float rs = p0 + p1;
#pragma unroll
                for (int off = 16; off >= 1; off >>= 1)
                    rs += __shfl_xor_sync(0xffffffffu, rs, off);
                l_i[i] = l_i[i] * alpha + rs;
                m_i[i] = m_new;
#pragma unroll
                for (int j = 0; j < 4; j++) acc[i][j] *= alpha;
                sS[(wid * 4 + i) * TK + lane]      = p0;
                sS[(wid * 4 + i) * TK + lane + 32] = p1;
            }
            __syncwarp();  // sS rows are warp-private; warp sync suffices

            // ---- O += P V  (each thread: 4 rows x 4 cols @ lane*4) ----
#pragma unroll 4
            for (int c = 0; c < TK; c++) {
                float4 vv = *(float4*)&sV[c * HH + lane * 4];
#pragma unroll
                for (int i = 0; i < 4; i++) {
                    float p = sS[(wid * 4 + i) * TK + c];
                    acc[i][0] += p * vv.x;
                    acc[i][1] += p * vv.y;
                    acc[i][2] += p * vv.z;
                    acc[i][3] += p * vv.w;
                }
            }
        }

        // ---- epilogue: normalize + write ----
#pragma unroll
        for (int i = 0; i < 4; i++) {
            const int row = q0 + wid * 4 + i;
            const float inv = 1.f / l_i[i];
            float4 o = make_float4(acc[i][0] * inv, acc[i][1] * inv,
                                   acc[i][2] * inv, acc[i][3] * inv);
            *(float4*)(out + ((size_t)b * SS_ + row) * HH + lane * 4) = o;
        }
    }
}

// ---------------------------------------------------------------------------
extern "C" void kernel_launch(void* const* d_in, const int* in_sizes, int n_in,
                              void* d_out, int out_size)
{
    const float* x  = (const float*)d_in[0];
    const float* Wq = (const float*)d_in[1];
    const float* Wk = (const float*)d_in[2];
    const float* Wv = (const float*)d_in[3];
    float* out = (float*)d_out;

    const int smem_bytes = (32 * 128 + 128 * 65 + 64 * 128 + 32 * 64) * 4;  // 90624
    cudaFuncSetAttribute(attn_kernel, cudaFuncAttributeMaxDynamicSharedMemorySize,
                         smem_bytes);

    proj_kernel<<<dim3(8192 / 64, 3), 256>>>(x, Wq, Wk, Wv);
    attn_kernel<<<dim3(32, 4), 256, smem_bytes>>>(out);
}

// round 4
// speedup vs baseline: 1.7129x; 1.7129x over previous
#include <cuda_runtime.h>
#include <cstdint>

#define BB 4
#define SS_ 2048
#define EE 1024
#define HH 128

#define NEG_INF (-1e30f)

// Scratch for projected q/k/v (device globals: no allocation allowed).
__device__ float g_q[BB * SS_ * HH];
__device__ float g_k[BB * SS_ * HH];
__device__ float g_v[BB * SS_ * HH];

// ---------------------------------------------------------------------------
// Helpers
// ---------------------------------------------------------------------------
__device__ __forceinline__ uint32_t smem_u32(const void* p) {
    uint32_t a;
    asm("{ .reg .u64 t; cvta.to.shared.u64 t, %1; cvt.u32.u64 %0, t; }"
        : "=r"(a) : "l"(p));
    return a;
}
__device__ __forceinline__ uint32_t f2tf32(float f) {
    uint32_t r;
    asm("cvt.rna.tf32.f32 %0, %1;" : "=r"(r) : "f"(f));
    return r;
}
__device__ __forceinline__ void mma_tf32(float* d, const uint32_t* a,
                                         const uint32_t* b) {
    asm volatile(
        "mma.sync.aligned.m16n8k8.row.col.f32.tf32.tf32.f32 "
        "{%0,%1,%2,%3}, {%4,%5,%6,%7}, {%8,%9}, {%0,%1,%2,%3};"
        : "+f"(d[0]), "+f"(d[1]), "+f"(d[2]), "+f"(d[3])
        : "r"(a[0]), "r"(a[1]), "r"(a[2]), "r"(a[3]), "r"(b[0]), "r"(b[1]));
}
#define CP_ASYNC16(dst_u32, src) \
    asm volatile("cp.async.cg.shared.global [%0], [%1], 16;" :: "r"(dst_u32), "l"(src))
#define CP_COMMIT() asm volatile("cp.async.commit_group;" ::: "memory")
#define CP_WAIT(n)  asm volatile("cp.async.wait_group %0;" :: "n"(n) : "memory")

// ---------------------------------------------------------------------------
// Projection GEMM via mma.sync tf32.
// O[M,H] = X[M,E] @ W[E,H];  M = 8192.  Block = (m_tile, which).
// BM=128, BN=128(=H), BK=16.  256 thr = 8 warps in 2x4 grid; warp tile 64x32.
// Double-buffered cp.async pipeline.
// ---------------------------------------------------------------------------
#define PBM 128
#define PBK 16
#define SA_STR 20    // sA row stride (floats): conflict-free fragment reads
#define SB_STR 132   // sB row stride (floats)
#define NIT (EE / PBK)   // 64

__global__ __launch_bounds__(256, 1) void proj_mma_kernel(
    const float* __restrict__ x,
    const float* __restrict__ Wq,
    const float* __restrict__ Wk,
    const float* __restrict__ Wv)
{
    __shared__ float sA[2][PBM * SA_STR];   // [m][k] per stage
    __shared__ float sB[2][PBK * SB_STR];   // [k][n] per stage

    const int which = blockIdx.y;
    const float* __restrict__ W = (which == 0) ? Wq : (which == 1) ? Wk : Wv;
    float* __restrict__ O = (which == 0) ? g_q : (which == 1) ? g_k : g_v;

    const int m0   = blockIdx.x * PBM;
    const int tid  = threadIdx.x;
    const int wid  = tid >> 5;
    const int lane = tid & 31;
    const int g    = lane >> 2;   // groupID 0..7
    const int tig  = lane & 3;    // thread-in-group 0..3
    const int wm   = wid & 1;     // warp row (2)
    const int wn   = wid >> 1;    // warp col (4)

    // cp.async loaders: A = 512 float4 (2/thread), B = 512 float4 (2/thread)
    const int ar = tid >> 1;          // A row handled twice per thread via p
    (void)ar;

    auto load_tiles = [&](int st, int k0) {
#pragma unroll
        for (int p = 0; p < 2; p++) {
            int idx = p * 256 + tid;
            int r = idx >> 2, q = idx & 3;                  // A: 128 x 4 float4
            CP_ASYNC16(smem_u32(&sA[st][r * SA_STR + q * 4]),
                       x + (size_t)(m0 + r) * EE + k0 + q * 4);
            int br = idx >> 5, bq = idx & 31;               // B: 16 x 32 float4
            CP_ASYNC16(smem_u32(&sB[st][br * SB_STR + bq * 4]),
                       W + (size_t)(k0 + br) * HH + bq * 4);
        }
    };

    float acc[4][4][4];
#pragma unroll
    for (int i = 0; i < 4; i++)
#pragma unroll
        for (int j = 0; j < 4; j++)
#pragma unroll
            for (int r = 0; r < 4; r++) acc[i][j][r] = 0.f;

    load_tiles(0, 0);
    CP_COMMIT();

    for (int it = 0; it < NIT; it++) {
        const int st = it & 1;
        if (it + 1 < NIT) {
            load_tiles((it + 1) & 1, (it + 1) * PBK);
            CP_COMMIT();
            CP_WAIT(1);
        } else {
            CP_WAIT(0);
        }
        __syncthreads();

        const float* A = sA[st];
        const float* Bt = sB[st];
#pragma unroll
        for (int ks = 0; ks < 2; ks++) {
            const int kb = ks * 8;
            uint32_t af[4][4];
#pragma unroll
            for (int mt = 0; mt < 4; mt++) {
                const int row = wm * 64 + mt * 16 + g;
                af[mt][0] = f2tf32(A[row * SA_STR + kb + tig]);
                af[mt][1] = f2tf32(A[(row + 8) * SA_STR + kb + tig]);
                af[mt][2] = f2tf32(A[row * SA_STR + kb + tig + 4]);
                af[mt][3] = f2tf32(A[(row + 8) * SA_STR + kb + tig + 4]);
            }
            uint32_t bf[4][2];
#pragma unroll
            for (int nt = 0; nt < 4; nt++) {
                const int col = wn * 32 + nt * 8 + g;
                bf[nt][0] = f2tf32(Bt[(kb + tig) * SB_STR + col]);
                bf[nt][1] = f2tf32(Bt[(kb + tig + 4) * SB_STR + col]);
            }
#pragma unroll
            for (int mt = 0; mt < 4; mt++)
#pragma unroll
                for (int nt = 0; nt < 4; nt++)
                    mma_tf32(acc[mt][nt], af[mt], bf[nt]);
        }
        __syncthreads();
    }

    // Epilogue: D fragment -> gmem.  d0,d1: (row g, cols tig*2,+1); d2,d3: row g+8.
#pragma unroll
    for (int mt = 0; mt < 4; mt++) {
        const int row = m0 + wm * 64 + mt * 16 + g;
#pragma unroll
        for (int nt = 0; nt < 4; nt++) {
            const int col = wn * 32 + nt * 8 + tig * 2;
            *(float2*)(O + (size_t)row * HH + col) =
                make_float2(acc[mt][nt][0], acc[mt][nt][1]);
            *(float2*)(O + (size_t)(row + 8) * HH + col) =
                make_float2(acc[mt][nt][2], acc[mt][nt][3]);
        }
    }
}

// ---------------------------------------------------------------------------
// Flash attention, fp32, causal (unchanged from R1 — passed at 201.6us).
// ---------------------------------------------------------------------------
__global__ __launch_bounds__(256, 1) void attn_kernel(float* __restrict__ out)
{
    constexpr int TQ = 32;
    constexpr int TK = 64;
    constexpr int KSTR = 65;

    extern __shared__ float sm[];
    float* sQ  = sm;
    float* sKT = sQ + TQ * HH;
    float* sV  = sKT + HH * KSTR;
    float* sS  = sV + TK * HH;

    const int b    = blockIdx.y;
    const int pr   = blockIdx.x;
    const int tid  = threadIdx.x;
    const int wid  = tid >> 5;
    const int lane = tid & 31;

    const float scale = 0.08838834764831845f;

    const float* __restrict__ qbase = g_q + (size_t)b * SS_ * HH;
    const float* __restrict__ kbase = g_k + (size_t)b * SS_ * HH;
    const float* __restrict__ vbase = g_v + (size_t)b * SS_ * HH;

    for (int half = 0; half < 2; half++) {
        const int t  = (half == 0) ? pr : (63 - pr);
        const int q0 = t * TQ;

        __syncthreads();

#pragma unroll
        for (int p = 0; p < 4; p++) {
            int idx = p * 256 + tid;
            int row = idx >> 5;
            int hq  = idx & 31;
            *(float4*)&sQ[row * HH + hq * 4] =
                *(const float4*)(qbase + (size_t)(q0 + row) * HH + hq * 4);
        }

        float m_i[4], l_i[4], acc[4][4];
#pragma unroll
        for (int i = 0; i < 4; i++) {
            m_i[i] = NEG_INF;
            l_i[i] = 0.f;
#pragma unroll
            for (int j = 0; j < 4; j++) acc[i][j] = 0.f;
        }

        const int nkt = (q0 + TQ - 1) / TK + 1;
        for (int kt = 0; kt < nkt; kt++) {
            const int k0 = kt * TK;
            __syncthreads();

#pragma unroll
            for (int p = 0; p < 8; p++) {
                int idx = p * 256 + tid;
                int row = idx >> 5;
                int hq  = idx & 31;
                float4 kv = *(const float4*)(kbase + (size_t)(k0 + row) * HH + hq * 4);
                sKT[(hq * 4 + 0) * KSTR + row] = kv.x;
                sKT[(hq * 4 + 1) * KSTR + row] = kv.y;
                sKT[(hq * 4 + 2) * KSTR + row] = kv.z;
                sKT[(hq * 4 + 3) * KSTR + row] = kv.w;
                *(float4*)&sV[row * HH + hq * 4] =
                    *(const float4*)(vbase + (size_t)(k0 + row) * HH + hq * 4);
            }
            __syncthreads();

            float s0[4] = {0.f, 0.f, 0.f, 0.f};
            float s1[4] = {0.f, 0.f, 0.f, 0.f};
#pragma unroll 4
            for (int h4 = 0; h4 < HH; h4 += 4) {
                float qrow[4][4];
#pragma unroll
                for (int i = 0; i < 4; i++) {
                    float4 qv = *(float4*)&sQ[(wid * 4 + i) * HH + h4];
                    qrow[i][0] = qv.x; qrow[i][1] = qv.y;
                    qrow[i][2] = qv.z; qrow[i][3] = qv.w;
                }
#pragma unroll
                for (int hh = 0; hh < 4; hh++) {
                    float kA = sKT[(h4 + hh) * KSTR + lane];
                    float kB = sKT[(h4 + hh) * KSTR + lane + 32];
#pragma unroll
                    for (int i = 0; i < 4; i++) {
                        s0[i] += qrow[i][hh] * kA;
                        s1[i] += qrow[i][hh] * kB;
                    }
                }
            }

            const int kc0 = k0 + lane;
            const int kc1 = k0 + lane + 32;
#pragma unroll
            for (int i = 0; i < 4; i++) {
                const int qi = q0 + wid * 4 + i;
                float v0 = (kc0 <= qi) ? s0[i] * scale : NEG_INF;
                float v1 = (kc1 <= qi) ? s1[i] * scale : NEG_INF;
                float mx = fmaxf(v0, v1);
#pragma unroll
                for (int off = 16; off >= 1; off >>= 1)
                    mx = fmaxf(mx, __shfl_xor_sync(0xffffffffu, mx, off));
                float m_new = fmaxf(m_i[i], mx);
                float alpha = __expf(m_i[i] - m_new);
                float p0 = __expf(v0 - m_new);
                float p1 = __expf(v1 - m_new);
                float rs = p0 + p1;
#pragma unroll
                for (int off = 16; off >= 1; off >>= 1)
                    rs += __shfl_xor_sync(0xffffffffu, rs, off);
                l_i[i] = l_i[i] * alpha + rs;
                m_i[i] = m_new;
#pragma unroll
                for (int j = 0; j < 4; j++) acc[i][j] *= alpha;
                sS[(wid * 4 + i) * TK + lane]      = p0;
                sS[(wid * 4 + i) * TK + lane + 32] = p1;
            }
            __syncwarp();

#pragma unroll 4
            for (int c = 0; c < TK; c++) {
                float4 vv = *(float4*)&sV[c * HH + lane * 4];
#pragma unroll
                for (int i = 0; i < 4; i++) {
                    float p = sS[(wid * 4 + i) * TK + c];
                    acc[i][0] += p * vv.x;
                    acc[i][1] += p * vv.y;
                    acc[i][2] += p * vv.z;
                    acc[i][3] += p * vv.w;
                }
            }
        }

#pragma unroll
        for (int i = 0; i < 4; i++) {
            const int row = q0 + wid * 4 + i;
            const float inv = 1.f / l_i[i];
            float4 o = make_float4(acc[i][0] * inv, acc[i][1] * inv,
                                   acc[i][2] * inv, acc[i][3] * inv);
            *(float4*)(out + ((size_t)b * SS_ + row) * HH + lane * 4) = o;
        }
    }
}

// ---------------------------------------------------------------------------
extern "C" void kernel_launch(void* const* d_in, const int* in_sizes, int n_in,
                              void* d_out, int out_size)
{
    const float* x  = (const float*)d_in[0];
    const float* Wq = (const float*)d_in[1];
    const float* Wk = (const float*)d_in[2];
    const float* Wv = (const float*)d_in[3];
    float* out = (float*)d_out;

    const int attn_smem = (32 * 128 + 128 * 65 + 64 * 128 + 32 * 64) * 4;  // 90624
    cudaFuncSetAttribute(attn_kernel, cudaFuncAttributeMaxDynamicSharedMemorySize,
                         attn_smem);

    proj_mma_kernel<<<dim3(8192 / PBM, 3), 256>>>(x, Wq, Wk, Wv);
    attn_kernel<<<dim3(32, 4), 256, attn_smem>>>(out);
}

// round 5
// speedup vs baseline: 3.1410x; 1.8337x over previous
#include <cuda_runtime.h>
#include <cstdint>

#define BB 4
#define SS_ 2048
#define EE 1024
#define HH 128

#define NEG_INF (-1e30f)

// Scratch for projected q/k/v (device globals: no allocation allowed).
__device__ float g_q[BB * SS_ * HH];
__device__ float g_k[BB * SS_ * HH];
__device__ float g_v[BB * SS_ * HH];

// ---------------------------------------------------------------------------
// Helpers
// ---------------------------------------------------------------------------
__device__ __forceinline__ uint32_t smem_u32(const void* p) {
    uint32_t a;
    asm("{ .reg .u64 t; cvta.to.shared.u64 t, %1; cvt.u32.u64 %0, t; }"
        : "=r"(a) : "l"(p));
    return a;
}
__device__ __forceinline__ uint32_t f2tf32(float f) {
    uint32_t r;
    asm("cvt.rna.tf32.f32 %0, %1;" : "=r"(r) : "f"(f));
    return r;
}
__device__ __forceinline__ void mma_tf32(float* d, const uint32_t* a,
                                         const uint32_t* b) {
    asm volatile(
        "mma.sync.aligned.m16n8k8.row.col.f32.tf32.tf32.f32 "
        "{%0,%1,%2,%3}, {%4,%5,%6,%7}, {%8,%9}, {%0,%1,%2,%3};"
        : "+f"(d[0]), "+f"(d[1]), "+f"(d[2]), "+f"(d[3])
        : "r"(a[0]), "r"(a[1]), "r"(a[2]), "r"(a[3]), "r"(b[0]), "r"(b[1]));
}
#define CP_ASYNC16(dst_u32, src) \
    asm volatile("cp.async.cg.shared.global [%0], [%1], 16;" :: "r"(dst_u32), "l"(src))
#define CP_COMMIT() asm volatile("cp.async.commit_group;" ::: "memory")
#define CP_WAIT(n)  asm volatile("cp.async.wait_group %0;" :: "n"(n) : "memory")
#define BAR_SYNC(id, n) asm volatile("bar.sync %0, %1;" :: "r"(id), "r"(n) : "memory")

// ---------------------------------------------------------------------------
// Projection GEMM via mma.sync tf32 (unchanged from R4 — 66us, passed).
// ---------------------------------------------------------------------------
#define PBM 128
#define PBK 16
#define SA_STR 20
#define SB_STR 132
#define NIT (EE / PBK)

__global__ __launch_bounds__(256, 1) void proj_mma_kernel(
    const float* __restrict__ x,
    const float* __restrict__ Wq,
    const float* __restrict__ Wk,
    const float* __restrict__ Wv)
{
    __shared__ float sA[2][PBM * SA_STR];
    __shared__ float sB[2][PBK * SB_STR];

    const int which = blockIdx.y;
    const float* __restrict__ W = (which == 0) ? Wq : (which == 1) ? Wk : Wv;
    float* __restrict__ O = (which == 0) ? g_q : (which == 1) ? g_k : g_v;

    const int m0   = blockIdx.x * PBM;
    const int tid  = threadIdx.x;
    const int wid  = tid >> 5;
    const int lane = tid & 31;
    const int g    = lane >> 2;
    const int tig  = lane & 3;
    const int wm   = wid & 1;
    const int wn   = wid >> 1;

    auto load_tiles = [&](int st, int k0) {
#pragma unroll
        for (int p = 0; p < 2; p++) {
            int idx = p * 256 + tid;
            int r = idx >> 2, q = idx & 3;
            CP_ASYNC16(smem_u32(&sA[st][r * SA_STR + q * 4]),
                       x + (size_t)(m0 + r) * EE + k0 + q * 4);
            int br = idx >> 5, bq = idx & 31;
            CP_ASYNC16(smem_u32(&sB[st][br * SB_STR + bq * 4]),
                       W + (size_t)(k0 + br) * HH + bq * 4);
        }
    };

    float acc[4][4][4];
#pragma unroll
    for (int i = 0; i < 4; i++)
#pragma unroll
        for (int j = 0; j < 4; j++)
#pragma unroll
            for (int r = 0; r < 4; r++) acc[i][j][r] = 0.f;

    load_tiles(0, 0);
    CP_COMMIT();

    for (int it = 0; it < NIT; it++) {
        const int st = it & 1;
        if (it + 1 < NIT) {
            load_tiles((it + 1) & 1, (it + 1) * PBK);
            CP_COMMIT();
            CP_WAIT(1);
        } else {
            CP_WAIT(0);
        }
        __syncthreads();

        const float* A = sA[st];
        const float* Bt = sB[st];
#pragma unroll
        for (int ks = 0; ks < 2; ks++) {
            const int kb = ks * 8;
            uint32_t af[4][4];
#pragma unroll
            for (int mt = 0; mt < 4; mt++) {
                const int row = wm * 64 + mt * 16 + g;
                af[mt][0] = f2tf32(A[row * SA_STR + kb + tig]);
                af[mt][1] = f2tf32(A[(row + 8) * SA_STR + kb + tig]);
                af[mt][2] = f2tf32(A[row * SA_STR + kb + tig + 4]);
                af[mt][3] = f2tf32(A[(row + 8) * SA_STR + kb + tig + 4]);
            }
            uint32_t bf[4][2];
#pragma unroll
            for (int nt = 0; nt < 4; nt++) {
                const int col = wn * 32 + nt * 8 + g;
                bf[nt][0] = f2tf32(Bt[(kb + tig) * SB_STR + col]);
                bf[nt][1] = f2tf32(Bt[(kb + tig + 4) * SB_STR + col]);
            }
#pragma unroll
            for (int mt = 0; mt < 4; mt++)
#pragma unroll
                for (int nt = 0; nt < 4; nt++)
                    mma_tf32(acc[mt][nt], af[mt], bf[nt]);
        }
        __syncthreads();
    }

#pragma unroll
    for (int mt = 0; mt < 4; mt++) {
        const int row = m0 + wm * 64 + mt * 16 + g;
#pragma unroll
        for (int nt = 0; nt < 4; nt++) {
            const int col = wn * 32 + nt * 8 + tig * 2;
            *(float2*)(O + (size_t)row * HH + col) =
                make_float2(acc[mt][nt][0], acc[mt][nt][1]);
            *(float2*)(O + (size_t)(row + 8) * HH + col) =
                make_float2(acc[mt][nt][2], acc[mt][nt][3]);
        }
    }
}

// ---------------------------------------------------------------------------
// Flash attention with tf32 mma.sync.
// TQ=32, TK=64.  256 thr = 8 warps: wm = wid>>2 (q-row group of 16),
// wn = wid&3.
// S gemm: warp (wm,wn) computes S[wm*16+16][wn*16+16] (2 n-tiles, 16 ksteps).
// PV gemm: warp (wm,wn) computes O[wm*16+16][wn*32+32] (4 n-tiles, 8 ksteps).
// K stored [key][h] stride 132  -> S B-frag  sK[n*132 + k]   (banks g*4+tig)
// V stored [key][h] stride 136  -> PV B-frag sV[k*136 + n]   (banks tig*8+g)
// P stored [q][key] stride 68   -> PV A-frag sP[m*68  + k]   (banks g*4+tig)
// ---------------------------------------------------------------------------
#define QSTR 132
#define KSTR 132
#define VSTR 136
#define PSTR 68
#define ATT_SMEM ((32 * QSTR + 64 * KSTR + 64 * VSTR + 32 * PSTR + 256) * 4)

__global__ __launch_bounds__(256, 1) void attn_tc_kernel(float* __restrict__ out)
{
    extern __shared__ uint32_t smA[];
    uint32_t* sQ = smA;                    // 32*132
    uint32_t* sK = sQ + 32 * QSTR;         // 64*132
    uint32_t* sV = sK + 64 * KSTR;         // 64*136
    uint32_t* sP = sV + 64 * VSTR;         // 32*68
    float* sRM = (float*)(sP + 32 * PSTR); // 128
    float* sRS = sRM + 128;                // 128

    const int b    = blockIdx.y;
    const int pr   = blockIdx.x;  // 0..31 -> q-tile pair (pr, 63-pr)
    const int tid  = threadIdx.x;
    const int wid  = tid >> 5;
    const int lane = tid & 31;
    const int g    = lane >> 2;
    const int tig  = lane & 3;
    const int wm   = wid >> 2;    // 0..1
    const int wn   = wid & 3;     // 0..3

    const float scale = 0.08838834764831845f;  // 1/sqrt(128)

    const float* __restrict__ qb = g_q + (size_t)b * SS_ * HH;
    const float* __restrict__ kb = g_k + (size_t)b * SS_ * HH;
    const float* __restrict__ vb = g_v + (size_t)b * SS_ * HH;

    for (int half = 0; half < 2; half++) {
        const int t  = (half == 0) ? pr : (63 - pr);
        const int q0 = t * 32;

        __syncthreads();  // prev half fully done with sQ/sK/sV

        // Load Q tile (32 x 128) as tf32
#pragma unroll
        for (int p = 0; p < 4; p++) {
            int idx = p * 256 + tid;
            int row = idx >> 5, hq = idx & 31;
            float4 qv = *(const float4*)(qb + (size_t)(q0 + row) * HH + hq * 4);
            uint4 u = make_uint4(f2tf32(qv.x), f2tf32(qv.y), f2tf32(qv.z), f2tf32(qv.w));
            *(uint4*)&sQ[row * QSTR + hq * 4] = u;
        }
        __syncthreads();

        // Resident Q fragments: 16 k-steps x 4 regs
        uint32_t aq[16][4];
        const int qrow = wm * 16 + g;
#pragma unroll
        for (int ks = 0; ks < 16; ks++) {
            aq[ks][0] = sQ[qrow * QSTR + ks * 8 + tig];
            aq[ks][1] = sQ[(qrow + 8) * QSTR + ks * 8 + tig];
            aq[ks][2] = sQ[qrow * QSTR + ks * 8 + tig + 4];
            aq[ks][3] = sQ[(qrow + 8) * QSTR + ks * 8 + tig + 4];
        }

        float m_i[2] = {NEG_INF, NEG_INF};
        float l_i[2] = {0.f, 0.f};
        float acc[4][4];
#pragma unroll
        for (int nt = 0; nt < 4; nt++)
#pragma unroll
            for (int r = 0; r < 4; r++) acc[nt][r] = 0.f;

        const int row0 = q0 + wm * 16 + g;   // global q row (and row0+8)
        const int nkt  = (q0 + 31) / 64 + 1;

        for (int kt = 0; kt < nkt; kt++) {
            const int k0 = kt * 64;
            __syncthreads();  // everyone done reading prev sK/sV

            // Load K,V tiles (64 x 128 each) as tf32
#pragma unroll
            for (int p = 0; p < 8; p++) {
                int idx = p * 256 + tid;
                int row = idx >> 5, hq = idx & 31;
                float4 kv = *(const float4*)(kb + (size_t)(k0 + row) * HH + hq * 4);
                *(uint4*)&sK[row * KSTR + hq * 4] =
                    make_uint4(f2tf32(kv.x), f2tf32(kv.y), f2tf32(kv.z), f2tf32(kv.w));
                float4 vv = *(const float4*)(vb + (size_t)(k0 + row) * HH + hq * 4);
                *(uint4*)&sV[row * VSTR + hq * 4] =
                    make_uint4(f2tf32(vv.x), f2tf32(vv.y), f2tf32(vv.z), f2tf32(vv.w));
            }
            __syncthreads();

            // ---- S = Q K^T : 2 n-tiles x 16 k-steps ----
            float sf[2][4];
#pragma unroll
            for (int nt = 0; nt < 2; nt++)
#pragma unroll
                for (int r = 0; r < 4; r++) sf[nt][r] = 0.f;
#pragma unroll
            for (int ks = 0; ks < 16; ks++) {
#pragma unroll
                for (int nt = 0; nt < 2; nt++) {
                    const int ncol = wn * 16 + nt * 8 + g;
                    uint32_t bf[2];
                    bf[0] = sK[ncol * KSTR + ks * 8 + tig];
                    bf[1] = sK[ncol * KSTR + ks * 8 + tig + 4];
                    mma_tf32(sf[nt], aq[ks], bf);
                }
            }

            // ---- mask + scale (values kept in regs) ----
            float mv[2][4];
#pragma unroll
            for (int nt = 0; nt < 2; nt++) {
#pragma unroll
                for (int j = 0; j < 2; j++) {
                    const int col = k0 + wn * 16 + nt * 8 + tig * 2 + j;
                    mv[nt][j]     = (col <= row0)     ? sf[nt][j] * scale     : NEG_INF;
                    mv[nt][j + 2] = (col <= row0 + 8) ? sf[nt][j + 2] * scale : NEG_INF;
                }
            }

            // ---- row max: quad reduce then cross-wn via smem ----
            float vx0 = fmaxf(fmaxf(mv[0][0], mv[0][1]), fmaxf(mv[1][0], mv[1][1]));
            float vx1 = fmaxf(fmaxf(mv[0][2], mv[0][3]), fmaxf(mv[1][2], mv[1][3]));
#pragma unroll
            for (int off = 1; off <= 2; off <<= 1) {
                vx0 = fmaxf(vx0, __shfl_xor_sync(0xffffffffu, vx0, off));
                vx1 = fmaxf(vx1, __shfl_xor_sync(0xffffffffu, vx1, off));
            }
            if (tig == 0) {
                sRM[wn * 32 + wm * 16 + g]     = vx0;
                sRM[wn * 32 + wm * 16 + g + 8] = vx1;
            }
            BAR_SYNC(1 + wm, 128);
            float mt0 = sRM[wm * 16 + g],      mt1 = sRM[wm * 16 + g + 8];
#pragma unroll
            for (int w = 1; w < 4; w++) {
                mt0 = fmaxf(mt0, sRM[w * 32 + wm * 16 + g]);
                mt1 = fmaxf(mt1, sRM[w * 32 + wm * 16 + g + 8]);
            }
            const float mn0 = fmaxf(m_i[0], mt0);
            const float mn1 = fmaxf(m_i[1], mt1);
            const float al0 = __expf(m_i[0] - mn0);
            const float al1 = __expf(m_i[1] - mn1);
            m_i[0] = mn0; m_i[1] = mn1;

            // ---- exp, P -> smem (tf32), partial sums ----
            float rs0 = 0.f, rs1 = 0.f;
#pragma unroll
            for (int nt = 0; nt < 2; nt++) {
#pragma unroll
                for (int j = 0; j < 2; j++) {
                    const int c = wn * 16 + nt * 8 + tig * 2 + j;
                    float p0 = __expf(mv[nt][j] - mn0);
                    float p1 = __expf(mv[nt][j + 2] - mn1);
                    rs0 += p0; rs1 += p1;
                    sP[(wm * 16 + g) * PSTR + c]     = f2tf32(p0);
                    sP[(wm * 16 + g + 8) * PSTR + c] = f2tf32(p1);
                }
            }
#pragma unroll
            for (int off = 1; off <= 2; off <<= 1) {
                rs0 += __shfl_xor_sync(0xffffffffu, rs0, off);
                rs1 += __shfl_xor_sync(0xffffffffu, rs1, off);
            }
            if (tig == 0) {
                sRS[wn * 32 + wm * 16 + g]     = rs0;
                sRS[wn * 32 + wm * 16 + g + 8] = rs1;
            }
            // rescale O accumulators while waiting
#pragma unroll
            for (int nt = 0; nt < 4; nt++) {
                acc[nt][0] *= al0; acc[nt][1] *= al0;
                acc[nt][2] *= al1; acc[nt][3] *= al1;
            }
            BAR_SYNC(1 + wm, 128);
            float ts0 = sRS[wm * 16 + g], ts1 = sRS[wm * 16 + g + 8];
#pragma unroll
            for (int w = 1; w < 4; w++) {
                ts0 += sRS[w * 32 + wm * 16 + g];
                ts1 += sRS[w * 32 + wm * 16 + g + 8];
            }
            l_i[0] = l_i[0] * al0 + ts0;
            l_i[1] = l_i[1] * al1 + ts1;

            // ---- O += P V : 4 n-tiles x 8 k-steps ----
#pragma unroll
            for (int ks = 0; ks < 8; ks++) {
                uint32_t ap[4];
                ap[0] = sP[(wm * 16 + g) * PSTR + ks * 8 + tig];
                ap[1] = sP[(wm * 16 + g + 8) * PSTR + ks * 8 + tig];
                ap[2] = sP[(wm * 16 + g) * PSTR + ks * 8 + tig + 4];
                ap[3] = sP[(wm * 16 + g + 8) * PSTR + ks * 8 + tig + 4];
#pragma unroll
                for (int nt = 0; nt < 4; nt++) {
                    const int ncol = wn * 32 + nt * 8 + g;
                    uint32_t bf[2];
                    bf[0] = sV[(ks * 8 + tig) * VSTR + ncol];
                    bf[1] = sV[(ks * 8 + tig + 4) * VSTR + ncol];
                    mma_tf32(acc[nt], ap, bf);
                }
            }
        }

        // ---- epilogue ----
        const float inv0 = 1.f / l_i[0];
        const float inv1 = 1.f / l_i[1];
#pragma unroll
        for (int nt = 0; nt < 4; nt++) {
            const int col = wn * 32 + nt * 8 + tig * 2;
            *(float2*)(out + ((size_t)b * SS_ + row0) * HH + col) =
                make_float2(acc[nt][0] * inv0, acc[nt][1] * inv0);
            *(float2*)(out + ((size_t)b * SS_ + row0 + 8) * HH + col) =
                make_float2(acc[nt][2] * inv1, acc[nt][3] * inv1);
        }
    }
}

// ---------------------------------------------------------------------------
extern "C" void kernel_launch(void* const* d_in, const int* in_sizes, int n_in,
                              void* d_out, int out_size)
{
    const float* x  = (const float*)d_in[0];
    const float* Wq = (const float*)d_in[1];
    const float* Wk = (const float*)d_in[2];
    const float* Wv = (const float*)d_in[3];
    float* out = (float*)d_out;

    cudaFuncSetAttribute(attn_tc_kernel, cudaFuncAttributeMaxDynamicSharedMemorySize,
                         ATT_SMEM);

    proj_mma_kernel<<<dim3(8192 / PBM, 3), 256>>>(x, Wq, Wk, Wv);
    attn_tc_kernel<<<dim3(32, 4), 256, ATT_SMEM>>>(out);
}

// round 10
// speedup vs baseline: 3.8312x; 1.2197x over previous
#include <cuda_runtime.h>
#include <cstdint>

#define BB 4
#define SS_ 2048
#define EE 1024
#define HH 128

#define NEG_INF (-1e30f)
#define QSCALE 0.08838834764831845f   // 1/sqrt(128)

// Scratch for projected q/k/v (device globals: no allocation allowed).
// Stored PRE-ROUNDED to tf32 (and g_q pre-scaled by 1/sqrt(128)).
__device__ float g_q[BB * SS_ * HH];
__device__ float g_k[BB * SS_ * HH];
__device__ float g_v[BB * SS_ * HH];

// ---------------------------------------------------------------------------
// Helpers
// ---------------------------------------------------------------------------
__device__ __forceinline__ uint32_t smem_u32(const void* p) {
    uint32_t a;
    asm("{ .reg .u64 t; cvta.to.shared.u64 t, %1; cvt.u32.u64 %0, t; }"
        : "=r"(a) : "l"(p));
    return a;
}
__device__ __forceinline__ uint32_t f2tf32(float f) {
    uint32_t r;
    asm("cvt.rna.tf32.f32 %0, %1;" : "=r"(r) : "f"(f));
    return r;
}
__device__ __forceinline__ void mma_tf32(float* d, const uint32_t* a,
                                         const uint32_t* b) {
    asm volatile(
        "mma.sync.aligned.m16n8k8.row.col.f32.tf32.tf32.f32 "
        "{%0,%1,%2,%3}, {%4,%5,%6,%7}, {%8,%9}, {%0,%1,%2,%3};"
        : "+f"(d[0]), "+f"(d[1]), "+f"(d[2]), "+f"(d[3])
        : "r"(a[0]), "r"(a[1]), "r"(a[2]), "r"(a[3]), "r"(b[0]), "r"(b[1]));
}
#define CP_ASYNC16(dst_u32, src) \
    asm volatile("cp.async.cg.shared.global [%0], [%1], 16;" :: "r"(dst_u32), "l"(src))
#define CP_COMMIT() asm volatile("cp.async.commit_group;" ::: "memory")
#define CP_WAIT(n)  asm volatile("cp.async.wait_group %0;" :: "n"(n) : "memory")
#define BAR_SYNC(id, n) asm volatile("bar.sync %0, %1;" :: "r"(id), "r"(n) : "memory")

// ---------------------------------------------------------------------------
// Fused projection GEMM: O[M, 384] = X[M,E] @ [Wq|Wk|Wv].
// BM=64, BN=384, BK=16.  128 CTAs = exactly 1 wave.  256 thr = 8 warps (2x4),
// warp tile 32x96 (2 m-tiles x 12 n-tiles).  Double-buffered cp.async.
// Epilogue stores tf32-ROUNDED floats (g_q also pre-scaled).
// ---------------------------------------------------------------------------
#define PBM 64
#define PBK 16
#define SA_STR 20
#define SB_STR 392
#define PROJ_SMEM ((2 * PBM * SA_STR + 2 * PBK * SB_STR) * 4)  // 60416 B
#define NIT (EE / PBK)   // 64

__global__ __launch_bounds__(256, 1) void proj_mma_kernel(
    const float* __restrict__ x,
    const float* __restrict__ Wq,
    const float* __restrict__ Wk,
    const float* __restrict__ Wv)
{
    extern __shared__ float psm[];
    float* sA = psm;                        // [2][64*20]
    float* sB = psm + 2 * PBM * SA_STR;     // [2][16*392]

    const int m0   = blockIdx.x * PBM;
    const int tid  = threadIdx.x;
    const int wid  = tid >> 5;
    const int lane = tid & 31;
    const int g    = lane >> 2;
    const int tig  = lane & 3;
    const int wm   = wid & 1;     // 2 row-warps (32 rows each)
    const int wn   = wid >> 1;    // 4 col-warps (96 cols each)

    const float* __restrict__ Ws[3] = {Wq, Wk, Wv};

    auto load_tiles = [&](int st, int k0) {
        // A: 64 rows x 4 float4 = 256 -> 1 per thread
        {
            int r = tid >> 2, qa = tid & 3;
            CP_ASYNC16(smem_u32(&sA[st * PBM * SA_STR + r * SA_STR + qa * 4]),
                       x + (size_t)(m0 + r) * EE + k0 + qa * 4);
        }
        // B: 16 rows x 96 float4 = 1536 -> 6 per thread
#pragma unroll
        for (int p = 0; p < 6; p++) {
            int idx = p * 256 + tid;
            int row = idx / 96, q = idx % 96;
            int col4 = q * 4;
            const float* W = Ws[col4 >> 7];
            int wcol = col4 & 127;
            CP_ASYNC16(smem_u32(&sB[st * PBK * SB_STR + row * SB_STR + col4]),
                       W + (size_t)(k0 + row) * HH + wcol);
        }
    };

    float acc[2][12][4];
#pragma unroll
    for (int i = 0; i < 2; i++)
#pragma unroll
        for (int j = 0; j < 12; j++)
#pragma unroll
            for (int r = 0; r < 4; r++) acc[i][j][r] = 0.f;

    load_tiles(0, 0);
    CP_COMMIT();

    for (int it = 0; it < NIT; it++) {
        const int st = it & 1;
        if (it + 1 < NIT) {
            load_tiles((it + 1) & 1, (it + 1) * PBK);
            CP_COMMIT();
            CP_WAIT(1);
        } else {
            CP_WAIT(0);
        }
        __syncthreads();

        const float* A  = sA + st * PBM * SA_STR;
        const float* Bt = sB + st * PBK * SB_STR;
#pragma unroll
        for (int ks = 0; ks < 2; ks++) {
            const int kb = ks * 8;
            uint32_t af[2][4];
#pragma unroll
            for (int mt = 0; mt < 2; mt++) {
                const int row = wm * 32 + mt * 16 + g;
                af[mt][0] = f2tf32(A[row * SA_STR + kb + tig]);
                af[mt][1] = f2tf32(A[(row + 8) * SA_STR + kb + tig]);
                af[mt][2] = f2tf32(A[row * SA_STR + kb + tig + 4]);
                af[mt][3] = f2tf32(A[(row + 8) * SA_STR + kb + tig + 4]);
            }
#pragma unroll
            for (int nt = 0; nt < 12; nt++) {
                const int col = wn * 96 + nt * 8 + g;
                uint32_t bf[2];
                bf[0] = f2tf32(Bt[(kb + tig) * SB_STR + col]);
                bf[1] = f2tf32(Bt[(kb + tig + 4) * SB_STR + col]);
#pragma unroll
                for (int mt = 0; mt < 2; mt++)
                    mma_tf32(acc[mt][nt], af[mt], bf);
            }
        }
        __syncthreads();
    }

    // Epilogue: route n-column to g_q/g_k/g_v, store tf32-rounded (Q scaled).
#pragma unroll
    for (int nt = 0; nt < 12; nt++) {
        const int col   = wn * 96 + nt * 8 + tig * 2;
        const int which = col >> 7;
        const int ocol  = col & 127;
        float* __restrict__ O = (which == 0) ? g_q : (which == 1) ? g_k : g_v;
        const float s = (which == 0) ? QSCALE : 1.f;
#pragma unroll
        for (int mt = 0; mt < 2; mt++) {
            const int row = m0 + wm * 32 + mt * 16 + g;
            float2 lo = make_float2(
                __uint_as_float(f2tf32(acc[mt][nt][0] * s)),
                __uint_as_float(f2tf32(acc[mt][nt][1] * s)));
            float2 hi = make_float2(
                __uint_as_float(f2tf32(acc[mt][nt][2] * s)),
                __uint_as_float(f2tf32(acc[mt][nt][3] * s)));
            *(float2*)(O + (size_t)row * HH + ocol)       = lo;
            *(float2*)(O + (size_t)(row + 8) * HH + ocol) = hi;
        }
    }
}

// ---------------------------------------------------------------------------
// Flash attention, tf32 mma, cp.async double-buffered K/V.
// Operands in g_q/g_k/g_v are already tf32-rounded (Q pre-scaled), so loads
// are raw cp.async — no conversion in this kernel except P.
// ---------------------------------------------------------------------------
#define QSTR 132
#define KSTR 132
#define VSTR 136
#define PSTR 68
#define ATT_SMEM ((32 * QSTR + 2 * 64 * KSTR + 2 * 64 * VSTR + 32 * PSTR + 256) * 4)

__global__ __launch_bounds__(256, 1) void attn_tc_kernel(float* __restrict__ out)
{
    extern __shared__ uint32_t smA[];
    uint32_t* sQ = smA;                        // 32*132
    uint32_t* sK = sQ + 32 * QSTR;             // [2][64*132]
    uint32_t* sV = sK + 2 * 64 * KSTR;         // [2][64*136]
    uint32_t* sP = sV + 2 * 64 * VSTR;         // 32*68
    float* sRM = (float*)(sP + 32 * PSTR);     // 128
    float* sRS = sRM + 128;                    // 128

    const int b    = blockIdx.y;
    const int pr   = blockIdx.x;  // 0..31 -> q-tile pair (pr, 63-pr)
    const int tid  = threadIdx.x;
    const int wid  = tid >> 5;
    const int lane = tid & 31;
    const int g    = lane >> 2;
    const int tig  = lane & 3;
    const int wm   = wid >> 2;    // 0..1
    const int wn   = wid & 3;     // 0..3

    const float* __restrict__ qb = g_q + (size_t)b * SS_ * HH;
    const float* __restrict__ kb = g_k + (size_t)b * SS_ * HH;
    const float* __restrict__ vb = g_v + (size_t)b * SS_ * HH;

    auto issue_kv = [&](int st, int k0) {
        // K,V tiles are 64 rows x 32 float4 each -> 2048 idx values -> p < 8.
#pragma unroll
        for (int p = 0; p < 8; p++) {
            int idx = p * 256 + tid;
            int row = idx >> 5, hq = idx & 31;
            CP_ASYNC16(smem_u32(&sK[st * 64 * KSTR + row * KSTR + hq * 4]),
                       kb + (size_t)(k0 + row) * HH + hq * 4);
            CP_ASYNC16(smem_u32(&sV[st * 64 * VSTR + row * VSTR + hq * 4]),
                       vb + (size_t)(k0 + row) * HH + hq * 4);
        }
    };

    for (int half = 0; half < 2; half++) {
        const int t  = (half == 0) ? pr : (63 - pr);
        const int q0 = t * 32;
        const int nkt = t / 2 + 1;

        __syncthreads();  // prev half fully done with all smem

        // Issue Q + first K/V tile as one group.
#pragma unroll
        for (int p = 0; p < 4; p++) {
            int idx = p * 256 + tid;
            int row = idx >> 5, hq = idx & 31;
            CP_ASYNC16(smem_u32(&sQ[row * QSTR + hq * 4]),
                       qb + (size_t)(q0 + row) * HH + hq * 4);
        }
        issue_kv(0, 0);
        CP_COMMIT();

        uint32_t aq[16][4];
        const int qrow = wm * 16 + g;

        float m_i[2] = {NEG_INF, NEG_INF};
        float l_i[2] = {0.f, 0.f};
        float acc[4][4];
#pragma unroll
        for (int nt = 0; nt < 4; nt++)
#pragma unroll
            for (int r = 0; r < 4; r++) acc[nt][r] = 0.f;

        const int row0 = q0 + wm * 16 + g;

        for (int kt = 0; kt < nkt; kt++) {
            const int buf = kt & 1;
            if (kt + 1 < nkt) {
                issue_kv((kt + 1) & 1, (kt + 1) * 64);
                CP_COMMIT();
                CP_WAIT(1);
            } else {
                CP_WAIT(0);
            }
            __syncthreads();

            if (kt == 0) {
#pragma unroll
                for (int ks = 0; ks < 16; ks++) {
                    aq[ks][0] = sQ[qrow * QSTR + ks * 8 + tig];
                    aq[ks][1] = sQ[(qrow + 8) * QSTR + ks * 8 + tig];
                    aq[ks][2] = sQ[qrow * QSTR + ks * 8 + tig + 4];
                    aq[ks][3] = sQ[(qrow + 8) * QSTR + ks * 8 + tig + 4];
                }
            }

            const uint32_t* Kb = sK + buf * 64 * KSTR;
            const uint32_t* Vb = sV + buf * 64 * VSTR;
            const int k0 = kt * 64;

            // ---- S = Q K^T : 2 n-tiles x 16 k-steps ----
            float sf[2][4];
#pragma unroll
            for (int nt = 0; nt < 2; nt++)
#pragma unroll
                for (int r = 0; r < 4; r++) sf[nt][r] = 0.f;
#pragma unroll
            for (int ks = 0; ks < 16; ks++) {
#pragma unroll
                for (int nt = 0; nt < 2; nt++) {
                    const int ncol = wn * 16 + nt * 8 + g;
                    uint32_t bf[2];
                    bf[0] = Kb[ncol * KSTR + ks * 8 + tig];
                    bf[1] = Kb[ncol * KSTR + ks * 8 + tig + 4];
                    mma_tf32(sf[nt], aq[ks], bf);
                }
            }

            // ---- causal mask (Q pre-scaled; no multiply needed) ----
            float mv[2][4];
#pragma unroll
            for (int nt = 0; nt < 2; nt++) {
#pragma unroll
                for (int j = 0; j < 2; j++) {
                    const int col = k0 + wn * 16 + nt * 8 + tig * 2 + j;
                    mv[nt][j]     = (col <= row0)     ? sf[nt][j]     : NEG_INF;
                    mv[nt][j + 2] = (col <= row0 + 8) ? sf[nt][j + 2] : NEG_INF;
                }
            }

            // ---- row max: quad reduce then cross-wn via smem ----
            float vx0 = fmaxf(fmaxf(mv[0][0], mv[0][1]), fmaxf(mv[1][0], mv[1][1]));
            float vx1 = fmaxf(fmaxf(mv[0][2], mv[0][3]), fmaxf(mv[1][2], mv[1][3]));
#pragma unroll
            for (int off = 1; off <= 2; off <<= 1) {
                vx0 = fmaxf(vx0, __shfl_xor_sync(0xffffffffu, vx0, off));
                vx1 = fmaxf(vx1, __shfl_xor_sync(0xffffffffu, vx1, off));
            }
            if (tig == 0) {
                sRM[wn * 32 + wm * 16 + g]     = vx0;
                sRM[wn * 32 + wm * 16 + g + 8] = vx1;
            }
            BAR_SYNC(1 + wm, 128);
            float mt0 = sRM[wm * 16 + g],      mt1 = sRM[wm * 16 + g + 8];
#pragma unroll
            for (int w = 1; w < 4; w++) {
                mt0 = fmaxf(mt0, sRM[w * 32 + wm * 16 + g]);
                mt1 = fmaxf(mt1, sRM[w * 32 + wm * 16 + g + 8]);
            }
            const float mn0 = fmaxf(m_i[0], mt0);
            const float mn1 = fmaxf(m_i[1], mt1);
            const float al0 = __expf(m_i[0] - mn0);
            const float al1 = __expf(m_i[1] - mn1);
            m_i[0] = mn0; m_i[1] = mn1;

            // ---- exp, P -> smem (tf32), partial sums ----
            float rs0 = 0.f, rs1 = 0.f;
#pragma unroll
            for (int nt = 0; nt < 2; nt++) {
#pragma unroll
                for (int j = 0; j < 2; j++) {
                    const int c = wn * 16 + nt * 8 + tig * 2 + j;
                    float p0 = __expf(mv[nt][j] - mn0);
                    float p1 = __expf(mv[nt][j + 2] - mn1);
                    rs0 += p0; rs1 += p1;
                    sP[(wm * 16 + g) * PSTR + c]     = f2tf32(p0);
                    sP[(wm * 16 + g + 8) * PSTR + c] = f2tf32(p1);
                }
            }
#pragma unroll
            for (int off = 1; off <= 2; off <<= 1) {
                rs0 += __shfl_xor_sync(0xffffffffu, rs0, off);
                rs1 += __shfl_xor_sync(0xffffffffu, rs1, off);
            }
            if (tig == 0) {
                sRS[wn * 32 + wm * 16 + g]     = rs0;
                sRS[wn * 32 + wm * 16 + g + 8] = rs1;
            }
            // rescale O accumulators while waiting
#pragma unroll
            for (int nt = 0; nt < 4; nt++) {
                acc[nt][0] *= al0; acc[nt][1] *= al0;
                acc[nt][2] *= al1; acc[nt][3] *= al1;
            }
            BAR_SYNC(1 + wm, 128);
            float ts0 = sRS[wm * 16 + g], ts1 = sRS[wm * 16 + g + 8];
#pragma unroll
            for (int w = 1; w < 4; w++) {
                ts0 += sRS[w * 32 + wm * 16 + g];
                ts1 += sRS[w * 32 + wm * 16 + g + 8];
            }
            l_i[0] = l_i[0] * al0 + ts0;
            l_i[1] = l_i[1] * al1 + ts1;

            // ---- O += P V : 4 n-tiles x 8 k-steps ----
#pragma unroll
            for (int ks = 0; ks < 8; ks++) {
                uint32_t ap[4];
                ap[0] = sP[(wm * 16 + g) * PSTR + ks * 8 + tig];
                ap[1] = sP[(wm * 16 + g + 8) * PSTR + ks * 8 + tig];
                ap[2] = sP[(wm * 16 + g) * PSTR + ks * 8 + tig + 4];
                ap[3] = sP[(wm * 16 + g + 8) * PSTR + ks * 8 + tig + 4];
#pragma unroll
                for (int nt = 0; nt < 4; nt++) {
                    const int ncol = wn * 32 + nt * 8 + g;
                    uint32_t bf[2];
                    bf[0] = Vb[(ks * 8 + tig) * VSTR + ncol];
                    bf[1] = Vb[(ks * 8 + tig + 4) * VSTR + ncol];
                    mma_tf32(acc[nt], ap, bf);
                }
            }
            __syncthreads();  // all reads of this buf done before next issue
        }

        // ---- epilogue ----
        const float inv0 = 1.f / l_i[0];
        const float inv1 = 1.f / l_i[1];
#pragma unroll
        for (int nt = 0; nt < 4; nt++) {
            const int col = wn * 32 + nt * 8 + tig * 2;
            *(float2*)(out + ((size_t)b * SS_ + row0) * HH + col) =
                make_float2(acc[nt][0] * inv0, acc[nt][1] * inv0);
            *(float2*)(out + ((size_t)b * SS_ + row0 + 8) * HH + col) =
                make_float2(acc[nt][2] * inv1, acc[nt][3] * inv1);
        }
    }
}

// ---------------------------------------------------------------------------
extern "C" void kernel_launch(void* const* d_in, const int* in_sizes, int n_in,
                              void* d_out, int out_size)
{
    const float* x  = (const float*)d_in[0];
    const float* Wq = (const float*)d_in[1];
    const float* Wk = (const float*)d_in[2];
    const float* Wv = (const float*)d_in[3];
    float* out = (float*)d_out;

    cudaFuncSetAttribute(proj_mma_kernel, cudaFuncAttributeMaxDynamicSharedMemorySize,
                         PROJ_SMEM);
    cudaFuncSetAttribute(attn_tc_kernel, cudaFuncAttributeMaxDynamicSharedMemorySize,
                         ATT_SMEM);

    proj_mma_kernel<<<8192 / PBM, 256, PROJ_SMEM>>>(x, Wq, Wk, Wv);
    attn_tc_kernel<<<dim3(32, 4), 256, ATT_SMEM>>>(out);
}